// round 9
// baseline (speedup 1.0000x reference)
#include <cuda_runtime.h>
#include <cstdint>

// KoopmanOperator: y_{t+1} = R(p(y_t)) applied 256 times to y_0 = x[:,0,:]
//   h = tanh(y @ W1^T + b1);  p = h @ W2^T + b2
//   mu = p[2i], om = p[2i+1]; e=exp(dt mu), c=cos(dt om), s=sin(dt om)
//   y'[2i] = e*(c*y[2i] - s*y[2i+1]);  y'[2i+1] = e*(s*y[2i] - c*y[2i+1])
//
// Layout (crossbar-optimized):
//   256 threads = 8 warps; warp w owns cols [8w, 8w+8); lane: rg=lane>>2 (0..7),
//   cg=lane&3 (0..3); lane tile = 4 rows (rg+8*rr) x 2 cols.
//   Y loads: per chunk 4 x LDS.128, each instr hits 8 CONSECUTIVE rows (rg across
//   lanes) at stride 68 -> banks 4*rg, conflict-free, full 128B/phase.
//   W loads: per chunk 2 x LDS.128, 4 distinct j per instr, bank-disjoint.
//   GEMV2 cols are the adjacent pair (2i,2i+1) -> update fused in registers,
//   no P buffer, 2 syncs/step.

#define D 64
#define T_STEPS 256
#define ROWS_PER_CTA 32
#define THREADS 256
#define STRIDE 68                        // floats; 272B row pitch, 16B-aligned
#define W_FLOATS (64 * STRIDE)
#define S_FLOATS (ROWS_PER_CTA * STRIDE)
#define SMEM_FLOATS (2 * W_FLOATS + 2 * S_FLOATS)   // W1, W2, Y, H
#define DT 0.01f

__device__ __forceinline__ void fma2(unsigned long long& d,
                                     unsigned long long a,
                                     unsigned long long b) {
    asm("fma.rn.f32x2 %0, %1, %2, %0;" : "+l"(d) : "l"(a), "l"(b));
}
__device__ __forceinline__ unsigned long long pack2(float x, float y) {
    unsigned long long u;
    asm("mov.b64 %0, {%1, %2};" : "=l"(u) : "f"(x), "f"(y));
    return u;
}
__device__ __forceinline__ float2 unpack2(unsigned long long u) {
    float2 f;
    asm("mov.b64 {%0, %1}, %2;" : "=f"(f.x), "=f"(f.y) : "l"(u));
    return f;
}

// Accurate fast tanh (~1e-6): EX2 + RCP. Safe over 256 recurrent steps.
__device__ __forceinline__ float tanh_acc(float x) {
    float ax = fabsf(x);
    float e  = __expf(-2.0f * ax);
    float t  = __fdividef(1.0f - e, 1.0f + e);
    return copysignf(t, x);
}

// Small-argument polynomials (|z| <~ 0.1-0.3): error < ~1e-6, pure FFMA.
__device__ __forceinline__ float exp_small(float z) {
    float p = fmaf(z, 1.0f / 120.0f, 1.0f / 24.0f);
    p = fmaf(z, p, 1.0f / 6.0f);
    p = fmaf(z, p, 0.5f);
    p = fmaf(z, p, 1.0f);
    return fmaf(z, p, 1.0f);
}
__device__ __forceinline__ float cos_small(float z2) {
    float p = fmaf(z2, -1.0f / 720.0f, 1.0f / 24.0f);
    p = fmaf(z2, p, -0.5f);
    return fmaf(z2, p, 1.0f);
}
__device__ __forceinline__ float sin_small(float z, float z2) {
    float p = fmaf(z2, 1.0f / 120.0f, -1.0f / 6.0f);
    return z * fmaf(z2, p, 1.0f);
}

// CTA-wide GEMV slice: out[rr][c] = sum_k Ws[col_c][k]*src[rg+8rr][k] + bias_c
__device__ __forceinline__ void gemv8(const float* __restrict__ Ws,
                                      const float* __restrict__ src,
                                      int c0, int c1, float b0, float b1,
                                      int rg, float out[4][2]) {
    unsigned long long acc[4][2];
#pragma unroll
    for (int rr = 0; rr < 4; rr++) {
        acc[rr][0] = pack2(b0, 0.0f);
        acc[rr][1] = pack2(b1, 0.0f);
    }
    const float* w0p = Ws + c0 * STRIDE;
    const float* w1p = Ws + c1 * STRIDE;
#pragma unroll
    for (int kc = 0; kc < D; kc += 4) {
        ulonglong2 y[4];
#pragma unroll
        for (int rr = 0; rr < 4; rr++)
            y[rr] = *reinterpret_cast<const ulonglong2*>(src + (rg + 8 * rr) * STRIDE + kc);
        ulonglong2 w0 = *reinterpret_cast<const ulonglong2*>(w0p + kc);
        ulonglong2 w1 = *reinterpret_cast<const ulonglong2*>(w1p + kc);
#pragma unroll
        for (int rr = 0; rr < 4; rr++) {
            fma2(acc[rr][0], w0.x, y[rr].x);
            fma2(acc[rr][0], w0.y, y[rr].y);
            fma2(acc[rr][1], w1.x, y[rr].x);
            fma2(acc[rr][1], w1.y, y[rr].y);
        }
    }
#pragma unroll
    for (int rr = 0; rr < 4; rr++) {
#pragma unroll
        for (int c = 0; c < 2; c++) {
            float2 v = unpack2(acc[rr][c]);
            out[rr][c] = v.x + v.y;
        }
    }
}

__global__ void __launch_bounds__(THREADS, 1)
koopman_kernel(const float* __restrict__ x,
               const float* __restrict__ W1g,
               const float* __restrict__ b1g,
               const float* __restrict__ W2g,
               const float* __restrict__ b2g,
               float* __restrict__ out) {
    extern __shared__ float sm[];
    float* W1s = sm;                       // [64][STRIDE]
    float* W2s = sm + W_FLOATS;            // [64][STRIDE]
    float* Ys  = sm + 2 * W_FLOATS;        // [32][STRIDE]
    float* Hs  = Ys + S_FLOATS;            // [32][STRIDE]

    const int tid  = threadIdx.x;
    const int w    = tid >> 5;             // warp 0..7 -> cols [8w, 8w+8)
    const int lane = tid & 31;
    const int rg   = lane >> 2;            // 0..7
    const int cg   = lane & 3;             // 0..3

    // GEMV1 cols (no pairing needed): c0a = 8w+cg, c1a = 8w+4+cg
    const int c0a = 8 * w + cg;
    const int c1a = 8 * w + 4 + cg;
    // GEMV2 cols: adjacent even/odd pair for in-register update
    const int j0 = 8 * w + 2 * cg;
    const int j1 = j0 + 1;

    const int rowbase = blockIdx.x * ROWS_PER_CTA;

    // ---- one-time init: weights (padded) + y0 into smem ----
    for (int i = tid; i < D * D; i += THREADS) {
        int j = i >> 6, k = i & 63;
        W1s[j * STRIDE + k] = W1g[i];
        W2s[j * STRIDE + k] = W2g[i];
    }
    for (int i = tid; i < ROWS_PER_CTA * D; i += THREADS) {
        int r = i >> 6, k = i & 63;
        Ys[r * STRIDE + k] = x[(size_t)(rowbase + r) * (T_STEPS * D) + k];
    }
    const float b1a = b1g[c0a], b1b = b1g[c1a];
    const float b2a = b2g[j0],  b2b = b2g[j1];
    __syncthreads();

    for (int t = 0; t < T_STEPS; t++) {
        // ---- GEMV1 + tanh -> Hs ----
        float h[4][2];
        gemv8(W1s, Ys, c0a, c1a, b1a, b1b, rg, h);
#pragma unroll
        for (int rr = 0; rr < 4; rr++) {
            const int r = rg + 8 * rr;
            Hs[r * STRIDE + c0a] = tanh_acc(h[rr][0]);
            Hs[r * STRIDE + c1a] = tanh_acc(h[rr][1]);
        }
        __syncthreads();   // Hs complete; all Ys reads of GEMV1 done

        // ---- GEMV2 (pair cols) + fused update, in registers ----
        float p[4][2];
        gemv8(W2s, Hs, j0, j1, b2a, b2b, rg, p);
#pragma unroll
        for (int rr = 0; rr < 4; rr++) {
            const int r = rg + 8 * rr;
            float zmu = DT * p[rr][0];
            float zom = DT * p[rr][1];
            float e  = exp_small(zmu);
            float z2 = zom * zom;
            float c  = cos_small(z2);
            float s  = sin_small(zom, z2);
            float2 y = *reinterpret_cast<const float2*>(Ys + r * STRIDE + 2 * j0 - j0); // see below
            // (2*j0 - j0 == j0; y pair lives at cols (j0, j1) of the state)
            float n0 = e * (c * y.x - s * y.y);
            float n1 = e * (s * y.x - c * y.y);   // reference: s*y0 - c*y1
            *reinterpret_cast<float2*>(Ys + r * STRIDE + j0) = make_float2(n0, n1);
            const size_t ob = ((size_t)(rowbase + r) * T_STEPS + t) * D + j0;
            *reinterpret_cast<float2*>(out + ob) = make_float2(n0, n1);
        }
        __syncthreads();   // Ys updated before next step's GEMV1
    }
}

extern "C" void kernel_launch(void* const* d_in, const int* in_sizes, int n_in,
                              void* d_out, int out_size) {
    const float* x  = (const float*)d_in[0];
    const float* W1 = (const float*)d_in[1];
    const float* b1 = (const float*)d_in[2];
    const float* W2 = (const float*)d_in[3];
    const float* b2 = (const float*)d_in[4];
    float* out = (float*)d_out;

    const int smem_bytes = SMEM_FLOATS * (int)sizeof(float);   // 52224 B
    cudaFuncSetAttribute(koopman_kernel,
                         cudaFuncAttributeMaxDynamicSharedMemorySize, smem_bytes);

    koopman_kernel<<<128, THREADS, smem_bytes>>>(x, W1, b1, W2, b2, out);
}

// round 10
// speedup vs baseline: 1.0826x; 1.0826x over previous
#include <cuda_runtime.h>
#include <cstdint>

// KoopmanOperator: y_{t+1} = R(p(y_t)), 256 steps, y_0 = x[:,0,:]
//   h = tanh(y @ W1^T + b1);  p = h @ W2^T + b2
//   mu=p[2i], om=p[2i+1]; e=exp(dt*mu), c=cos(dt*om), s=sin(dt*om)
//   y'[2i] = e*(c*y0 - s*y1);  y'[2i+1] = e*(s*y0 - c*y1)   (per reference)
//
// Structure: 256 CTAs x 16 rows, 128 threads (4 warps). Loaded SMs host 2
// BARRIER-INDEPENDENT CTAs (8 warps, 2/SMSP) for latency hiding.
// Warp tile 8 rows x 32 cols (2 row-groups x 2 col-groups), lane tile 4r x 2c.
//   Y loads: 2 distinct addrs/warp-instr (broadcast) -> 1 phase.
//   W loads: 16 distinct 16B addrs -> 2 phases (deg-2 banks by construction;
//            W2 stored even/odd-permuted so pair-columns also hit deg 2).
// Phases/step/SM = FMA-issue floor = 2048 cyc (balanced).
// GEMV2 columns are the adjacent pair (2m, 2m+1) -> update fused in registers,
// no P buffer, 2 syncthreads/step.

#define D 64
#define T_STEPS 256
#define ROWS_PER_CTA 16
#define THREADS 128
#define NCTA 256
#define STRIDE 68                          // floats; 272B pitch, 16B-aligned
#define W_FLOATS (64 * STRIDE)
#define S_FLOATS (ROWS_PER_CTA * STRIDE)
#define SMEM_FLOATS (2 * W_FLOATS + 2 * S_FLOATS)   // W1, W2, Y, H = 10880 f
#define DT 0.01f

__device__ __forceinline__ void fma2(unsigned long long& d,
                                     unsigned long long a,
                                     unsigned long long b) {
    asm("fma.rn.f32x2 %0, %1, %2, %0;" : "+l"(d) : "l"(a), "l"(b));
}
__device__ __forceinline__ unsigned long long pack2(float x, float y) {
    unsigned long long u;
    asm("mov.b64 %0, {%1, %2};" : "=l"(u) : "f"(x), "f"(y));
    return u;
}
__device__ __forceinline__ float2 unpack2(unsigned long long u) {
    float2 f;
    asm("mov.b64 {%0, %1}, %2;" : "=f"(f.x), "=f"(f.y) : "l"(u));
    return f;
}

// Accurate fast tanh (~1e-6): EX2 + RCP. Safe over 256 recurrent steps.
__device__ __forceinline__ float tanh_acc(float x) {
    float ax = fabsf(x);
    float e  = __expf(-2.0f * ax);
    float t  = __fdividef(1.0f - e, 1.0f + e);
    return copysignf(t, x);
}
// Small-argument Taylor (|z| <~ 0.3): error < 1e-7, pure FFMA.
__device__ __forceinline__ float exp_small(float z) {
    float p = fmaf(z, 1.0f / 120.0f, 1.0f / 24.0f);
    p = fmaf(z, p, 1.0f / 6.0f);
    p = fmaf(z, p, 0.5f);
    p = fmaf(z, p, 1.0f);
    return fmaf(z, p, 1.0f);
}
__device__ __forceinline__ float cos_small(float z2) {
    float p = fmaf(z2, -1.0f / 720.0f, 1.0f / 24.0f);
    p = fmaf(z2, p, -0.5f);
    return fmaf(z2, p, 1.0f);
}
__device__ __forceinline__ float sin_small(float z, float z2) {
    float p = fmaf(z2, 1.0f / 120.0f, -1.0f / 6.0f);
    return z * fmaf(z2, p, 1.0f);
}

// GEMV slice: for 4 rows (rows[i]) and 2 weight rows (wA, wB precomputed
// row pointers), out[i][c] = bias_c + sum_k w_c[k] * src[rows[i]][k].
__device__ __forceinline__ void gemv_slice(const float* __restrict__ wA,
                                           const float* __restrict__ wB,
                                           const float* __restrict__ src,
                                           const int rows[4],
                                           float bA, float bB,
                                           float out[4][2]) {
    unsigned long long acc[4][2];
#pragma unroll
    for (int i = 0; i < 4; i++) {
        acc[i][0] = pack2(bA, 0.0f);
        acc[i][1] = pack2(bB, 0.0f);
    }
#pragma unroll
    for (int kc = 0; kc < D; kc += 4) {
        ulonglong2 y[4];
#pragma unroll
        for (int i = 0; i < 4; i++)
            y[i] = *reinterpret_cast<const ulonglong2*>(src + rows[i] * STRIDE + kc);
        ulonglong2 wa = *reinterpret_cast<const ulonglong2*>(wA + kc);
        ulonglong2 wb = *reinterpret_cast<const ulonglong2*>(wB + kc);
#pragma unroll
        for (int i = 0; i < 4; i++) {
            fma2(acc[i][0], wa.x, y[i].x);
            fma2(acc[i][0], wa.y, y[i].y);
            fma2(acc[i][1], wb.x, y[i].x);
            fma2(acc[i][1], wb.y, y[i].y);
        }
    }
#pragma unroll
    for (int i = 0; i < 4; i++) {
#pragma unroll
        for (int c = 0; c < 2; c++) {
            float2 v = unpack2(acc[i][c]);
            out[i][c] = v.x + v.y;
        }
    }
}

__global__ void __launch_bounds__(THREADS, 2)
koopman_kernel(const float* __restrict__ x,
               const float* __restrict__ W1g,
               const float* __restrict__ b1g,
               const float* __restrict__ W2g,
               const float* __restrict__ b2g,
               float* __restrict__ out) {
    extern __shared__ float sm[];
    float* W1s = sm;                       // [64][STRIDE], natural order
    float* W2s = sm + W_FLOATS;            // [64][STRIDE], even/odd permuted
    float* Ys  = sm + 2 * W_FLOATS;        // [16][STRIDE]
    float* Hs  = Ys + S_FLOATS;            // [16][STRIDE]

    const int tid  = threadIdx.x;
    const int w    = tid >> 5;             // 0..3
    const int lane = tid & 31;
    const int wr   = w >> 1;               // row-group 0..1  -> rows [8wr, 8wr+8)
    const int wc   = w & 1;                // col-group 0..1  -> cols [32wc, 32wc+32)
    const int lr   = lane >> 4;            // 0..1
    const int lc   = lane & 15;            // 0..15

    int rows[4];
#pragma unroll
    for (int i = 0; i < 4; i++) rows[i] = 8 * wr + lr + 2 * i;

    // GEMV1 columns (no pairing constraint)
    const int c0 = 32 * wc + lc;
    const int c1 = 32 * wc + 16 + lc;
    // GEMV2: adjacent pair (2m, 2m+1); W2 stored at slots m and 32+m
    const int m  = 16 * wc + lc;           // 0..31
    const int j0 = 2 * m;

    const int rowbase = blockIdx.x * ROWS_PER_CTA;

    // ---- one-time init ----
    for (int i = tid; i < D * D; i += THREADS) {
        int j = i >> 6, k = i & 63;
        W1s[j * STRIDE + k] = W1g[i];
        int slot = (j >> 1) + (j & 1) * 32;            // even cols 0..31, odd 32..63
        W2s[slot * STRIDE + k] = W2g[i];
    }
    for (int i = tid; i < ROWS_PER_CTA * D; i += THREADS) {
        int r = i >> 6, k = i & 63;
        Ys[r * STRIDE + k] = x[(size_t)(rowbase + r) * (T_STEPS * D) + k];
    }
    const float b1a = b1g[c0], b1b = b1g[c1];
    const float b2a = b2g[j0], b2b = b2g[j0 + 1];

    const float* w1a = W1s + c0 * STRIDE;
    const float* w1b = W1s + c1 * STRIDE;
    const float* w2a = W2s + m * STRIDE;          // col j0 = 2m
    const float* w2b = W2s + (32 + m) * STRIDE;   // col j1 = 2m+1
    __syncthreads();

    for (int t = 0; t < T_STEPS; t++) {
        // ---- GEMV1 + tanh -> Hs ----
        float h[4][2];
        gemv_slice(w1a, w1b, Ys, rows, b1a, b1b, h);
#pragma unroll
        for (int i = 0; i < 4; i++) {
            Hs[rows[i] * STRIDE + c0] = tanh_acc(h[i][0]);
            Hs[rows[i] * STRIDE + c1] = tanh_acc(h[i][1]);
        }
        __syncthreads();   // Hs complete; all GEMV1 reads of Ys done

        // ---- GEMV2 (pair columns) + fused update ----
        float p[4][2];
        gemv_slice(w2a, w2b, Hs, rows, b2a, b2b, p);
#pragma unroll
        for (int i = 0; i < 4; i++) {
            const int r = rows[i];
            float zmu = DT * p[i][0];
            float zom = DT * p[i][1];
            float e  = exp_small(zmu);
            float z2 = zom * zom;
            float c  = cos_small(z2);
            float s  = sin_small(zom, z2);
            float2 y = *reinterpret_cast<const float2*>(Ys + r * STRIDE + j0);
            float n0 = e * (c * y.x - s * y.y);
            float n1 = e * (s * y.x - c * y.y);   // reference: s*y0 - c*y1
            *reinterpret_cast<float2*>(Ys + r * STRIDE + j0) = make_float2(n0, n1);
            const size_t ob = ((size_t)(rowbase + r) * T_STEPS + t) * D + j0;
            *reinterpret_cast<float2*>(out + ob) = make_float2(n0, n1);
        }
        __syncthreads();   // Ys fully updated before next step's GEMV1
    }
}

extern "C" void kernel_launch(void* const* d_in, const int* in_sizes, int n_in,
                              void* d_out, int out_size) {
    const float* x  = (const float*)d_in[0];
    const float* W1 = (const float*)d_in[1];
    const float* b1 = (const float*)d_in[2];
    const float* W2 = (const float*)d_in[3];
    const float* b2 = (const float*)d_in[4];
    float* out = (float*)d_out;

    const int smem_bytes = SMEM_FLOATS * (int)sizeof(float);   // 43520 B
    cudaFuncSetAttribute(koopman_kernel,
                         cudaFuncAttributeMaxDynamicSharedMemorySize, smem_bytes);

    // 4096 rows / 16 per CTA = 256 CTAs; 2 barrier-independent CTAs per SM.
    koopman_kernel<<<NCTA, THREADS, smem_bytes>>>(x, W1, b1, W2, b2, out);
}